// round 15
// baseline (speedup 1.0000x reference)
#include <cuda_runtime.h>
#include <cuda_bf16.h>
#include <math_constants.h>
#include <cstdint>

// Problem constants
#define NB   16
#define NC   1024
#define NT   16
#define NP   360          // H*W = 12*30
#define NK   120          // top-k
#define ROWS 482          // 1 + 120 + 1 + 360
#define TSTRIDE ((size_t)NT * NP)   // 5760 floats between consecutive c

// Block roles, dispatched in dependency order: tiles -> sorts -> gathers
#define N_TILE   1536                // 32ct x 3pt x 16b
#define BID_SORT N_TILE              // 16 sort blocks
#define BID_GATH (N_TILE + NB)       // 1920 gather blocks (120 ranks x 16 b)
#define GRID_ALL (BID_GATH + NK * NB)

// smem layout (floats): t0 tiles | t1 tiles | part | cls_s
#define T0OFF   0
#define T1OFF   4228
#define PARTOFF 8456
#define CLSOFF  9608
#define SBUF_FLOATS 9640             // 38.56 KB < 48 KB static limit

// Scratch (no device allocation allowed -> __device__ globals)
__device__ __align__(16) float g_xt0[NB][NP][NC];    // 23.6 MB f0 transposed
__device__ __align__(16) float g_spart[NB][32][NP];  // partial scores per ct
__device__ int g_topk[NB][128];
__device__ int g_cnt[NB * 32];    // per-b tile counters  (128B padded), init 0
__device__ int g_flag[NB * 32];   // per-b sort-done flag  (128B padded), init 0
__device__ int g_done[NB * 32];   // per-b gather counters (128B padded), init 0

// ---------------------------------------------------------------------------
// ONE kernel. Tile block (b,ct,pt): paired f0+f1 loads (activation sharing),
// scores + xt0 (dense 128B segs) from f0, out rows 122+ from f1, release cnt.
// Sort block (b): spin cnt==96, reduce, bitonic 512 (desc, idx-asc tiebreak),
// topk + cls rows, release flag, reset cnt. Gather block (b,rank): spin flag,
// copy xt0 row (written moments ago, same kernel) to out row 1+rank.
// ---------------------------------------------------------------------------
__global__ void __launch_bounds__(256) k_all(const float* __restrict__ x,
                                             const float* __restrict__ cls,
                                             float* __restrict__ out)
{
    __shared__ __align__(16) float sbuf[SBUF_FLOATS];
    const int bid = blockIdx.x;
    const int tid = threadIdx.x;

    if (bid < N_TILE) {
        // ================= tile path =======================================
        const int ct  = bid & 31;            // c tile of 32
        const int rem = bid >> 5;
        const int pt  = rem % 3;             // p tile of 128
        const int b   = rem / 3;             // 0..15

        float* t0    = sbuf + T0OFF;         // [4][1057], stride 1057==1 mod 32
        float* t1    = sbuf + T1OFF;
        float* part  = sbuf + PARTOFF;       // [128][9]
        float* cls_s = sbuf + CLSOFF;        // [32]

        const int pbase = pt * 128;
        const size_t xoff = ((size_t)b * NC + ct * 32) * TSTRIDE;

        if (tid < 32)
            cls_s[tid] = cls[b * (NT * NC) + ct * 32 + tid];   // t=0 cls

        // ---- paired f0+f1 tile loads (adjacent issue -> shared activation)
        {
            const float* x0 = x + xoff;        // t=0
            const float* x1 = x + xoff + NP;   // t=1 (1440B after f0 per c-row)
            #pragma unroll
            for (int i = 0; i < 4; ++i) {
                const int s  = tid + 256 * i;
                const int cl = s >> 5;           // 0..31
                const int pq = s & 31;           // 0..31
                const int p  = pbase + pq * 4;
                if (p < NP) {
                    const float4 v0 = *reinterpret_cast<const float4*>(
                        x0 + (size_t)cl * TSTRIDE + p);
                    const float4 v1 = *reinterpret_cast<const float4*>(
                        x1 + (size_t)cl * TSTRIDE + p);
                    const int sidx = cl * 33 + pq;
                    t0[0 * 1057 + sidx] = v0.x;
                    t0[1 * 1057 + sidx] = v0.y;
                    t0[2 * 1057 + sidx] = v0.z;
                    t0[3 * 1057 + sidx] = v0.w;
                    t1[0 * 1057 + sidx] = v1.x;
                    t1[1 * 1057 + sidx] = v1.y;
                    t1[2 * 1057 + sidx] = v1.z;
                    t1[3 * 1057 + sidx] = v1.w;
                }
            }
        }
        __syncthreads();

        // ---- f0: transposed store to xt0 (128B segments) + c-quad dots ----
        #pragma unroll
        for (int i = 0; i < 4; ++i) {
            const int s  = tid + 256 * i;
            const int cq = s & 7;            // 0..7
            const int pl = s >> 3;           // 0..127
            const int pg = pbase + pl;
            if (pg < NP) {
                const int j  = pl & 3;
                const int pq = pl >> 2;
                float4 w;
                w.x = t0[j * 1057 + (4 * cq + 0) * 33 + pq];
                w.y = t0[j * 1057 + (4 * cq + 1) * 33 + pq];
                w.z = t0[j * 1057 + (4 * cq + 2) * 33 + pq];
                w.w = t0[j * 1057 + (4 * cq + 3) * 33 + pq];
                *reinterpret_cast<float4*>(&g_xt0[b][pg][ct * 32 + cq * 4]) = w;
                const float d = fmaf(cls_s[4 * cq + 0], w.x,
                                fmaf(cls_s[4 * cq + 1], w.y,
                                fmaf(cls_s[4 * cq + 2], w.z,
                                     cls_s[4 * cq + 3] * w.w)));
                part[pl * 9 + cq] = d;
            }
        }
        __syncthreads();

        // ---- reduce partials, release counter early ----
        if (tid < 128) {
            const int pg = pbase + tid;
            if (pg < NP) {
                const float* pr = &part[tid * 9];
                g_spart[b][ct][pg] = ((pr[0] + pr[1]) + (pr[2] + pr[3]))
                                   + ((pr[4] + pr[5]) + (pr[6] + pr[7]));
            }
        }
        __syncthreads();
        if (tid == 0)
            asm volatile("red.release.gpu.global.add.s32 [%0], 1;"
                         :: "l"(&g_cnt[b * 32]) : "memory");

        // ---- f1: transposed store to out rows 122..481 (t1 still valid) ---
        const size_t obase = (size_t)b * ROWS * NC;
        #pragma unroll
        for (int i = 0; i < 4; ++i) {
            const int s  = tid + 256 * i;
            const int cq = s & 7;
            const int pl = s >> 3;
            const int pg = pbase + pl;
            if (pg < NP) {
                const int j  = pl & 3;
                const int pq = pl >> 2;
                float4 w;
                w.x = t1[j * 1057 + (4 * cq + 0) * 33 + pq];
                w.y = t1[j * 1057 + (4 * cq + 1) * 33 + pq];
                w.z = t1[j * 1057 + (4 * cq + 2) * 33 + pq];
                w.w = t1[j * 1057 + (4 * cq + 3) * 33 + pq];
                *reinterpret_cast<float4*>(
                    out + obase + (size_t)(122 + pg) * NC + ct * 32 + cq * 4) = w;
            }
        }
    }
    else if (bid < BID_GATH) {
        // ================= sort path =======================================
        const int b = bid - BID_SORT;
        float* sv = sbuf;                                 // [512]
        int*   si = reinterpret_cast<int*>(sbuf + 512);   // [512]

        if (tid == 0) {
            int v;
            do {
                __nanosleep(64);
                asm volatile("ld.acquire.gpu.global.s32 %0, [%1];"
                             : "=r"(v) : "l"(&g_cnt[b * 32]) : "memory");
            } while (v < 96);   // 96 tile blocks per b
            g_cnt[b * 32] = 0;  // reset for next replay (no more increments)
        }
        __syncthreads();   // acquire propagates to all threads

        for (int e = tid; e < 512; e += 256) {
            float vsum = -CUDART_INF_F;
            if (e < NP) {
                float a0 = 0.f, a1 = 0.f, a2 = 0.f, a3 = 0.f;
                #pragma unroll
                for (int k = 0; k < 32; k += 4) {
                    a0 += g_spart[b][k + 0][e];
                    a1 += g_spart[b][k + 1][e];
                    a2 += g_spart[b][k + 2][e];
                    a3 += g_spart[b][k + 3][e];
                }
                vsum = (a0 + a1) + (a2 + a3);
            }
            sv[e] = vsum;
            si[e] = e;
        }
        __syncthreads();

        // bitonic sort 512 (desc score, asc idx tiebreak = lax.top_k)
        for (int k = 2; k <= 512; k <<= 1) {
            for (int j = k >> 1; j > 0; j >>= 1) {
                const int l = 2 * tid - (tid & (j - 1));   // l & j == 0
                const int m = l | j;
                const float a = sv[l], c = sv[m];
                const int   ia = si[l], ic = si[m];
                const bool a_after = (a < c) || (a == c && ia > ic);
                const bool dir_desc = ((l & k) == 0);
                if (dir_desc ? a_after : !a_after) {
                    sv[l] = c; sv[m] = a; si[l] = ic; si[m] = ia;
                }
                __syncthreads();
            }
        }

        if (tid < NK) g_topk[b][tid] = si[tid];

        // cls rows: row 0 = cls[b,0,:], row 121 = cls[b,1,:]
        const size_t obase = (size_t)b * ROWS * NC;
        const float4* c4 = reinterpret_cast<const float4*>(cls + (size_t)b * NT * NC);
        float4* o4 = reinterpret_cast<float4*>(out + obase);
        for (int c = tid; c < NC / 4; c += 256) {
            o4[c]                = c4[c];               // row 0   (t=0 cls)
            o4[121 * (NC/4) + c] = c4[(NC/4) + c];      // row 121 (t=1 cls)
        }

        __syncthreads();   // topk ordered before flag release
        if (tid == 0)
            asm volatile("red.release.gpu.global.add.s32 [%0], 1;"
                         :: "l"(&g_flag[b * 32]) : "memory");
    }
    else {
        // ================= gather path (dispatched last) ===================
        const int idx  = bid - BID_GATH;
        const int rank = idx % NK;       // 0..119
        const int b    = idx / NK;       // 0..15

        if (tid == 0) {
            int v;
            do {
                __nanosleep(128);
                asm volatile("ld.acquire.gpu.global.s32 %0, [%1];"
                             : "=r"(v) : "l"(&g_flag[b * 32]) : "memory");
            } while (v == 0);
        }
        __syncthreads();   // acquire propagates; topk/xt0 visible

        const int p = g_topk[b][rank];
        const float4 v = *reinterpret_cast<const float4*>(&g_xt0[b][p][tid * 4]);
        *reinterpret_cast<float4*>(
            out + ((size_t)b * ROWS + 1 + rank) * NC + tid * 4) = v;

        // last gather block of this b resets flag/done for the next replay
        if (tid == 0) {
            const int old = atomicAdd(&g_done[b * 32], 1);
            if (old == NK - 1) {
                g_done[b * 32] = 0;
                g_flag[b * 32] = 0;
            }
        }
    }
}

// ---------------------------------------------------------------------------
extern "C" void kernel_launch(void* const* d_in, const int* in_sizes, int n_in,
                              void* d_out, int out_size)
{
    const float* x   = (const float*)d_in[0];   // [16,1024,16,12,30]
    const float* cls = (const float*)d_in[1];   // [16,16,1024]
    float* out = (float*)d_out;                 // [16,482,1024]

    k_all<<<GRID_ALL, 256>>>(x, cls, out);
}

// round 16
// speedup vs baseline: 1.1413x; 1.1413x over previous
#include <cuda_runtime.h>
#include <cuda_bf16.h>
#include <math_constants.h>
#include <cstdint>

// Problem constants
#define NB   16
#define NC   1024
#define NT   16
#define NP   360          // H*W = 12*30
#define NK   120          // top-k
#define ROWS 482          // 1 + 120 + 1 + 360
#define TSTRIDE ((size_t)NT * NP)   // 5760 floats between consecutive c

// Scratch (no device allocation allowed -> __device__ globals)
__device__ __align__(16) float g_spart[NB][32][NP];   // partial scores per ct
__device__ int g_posmap[NB][NP];

// ---------------------------------------------------------------------------
// K1: scores in k_mid's geometry. Block (b, ct, pt) = 32c x 128p f0 tile:
// float4 loads -> conflict-free component-split smem -> in-tile c-quad dots
// (R14-verified math) -> g_spart[b][ct][p]. 1536 blocks, 8/SM, ~131KB in
// flight per SM (matching k_mid's observed 3.2 TB/s read shape).
// ---------------------------------------------------------------------------
__global__ void __launch_bounds__(256) k_scores(const float* __restrict__ x,
                                                const float* __restrict__ cls)
{
    __shared__ __align__(16) float tiles[4 * 1057];   // stride 1057 == 1 (mod 32)
    __shared__ float part[128 * 9];
    __shared__ float cls_s[32];

    const int ct  = blockIdx.x & 31;         // c tile of 32
    const int rem = blockIdx.x >> 5;
    const int pt  = rem % 3;                 // p tile of 128
    const int b   = rem / 3;                 // 0..15
    const int tid = threadIdx.x;

    const int pbase = pt * 128;
    const float* xbase = x + ((size_t)b * NC + ct * 32) * TSTRIDE;  // t=0

    if (tid < 32)
        cls_s[tid] = cls[b * (NT * NC) + ct * 32 + tid];   // t=0 cls

    #pragma unroll
    for (int i = 0; i < 4; ++i) {
        const int s  = tid + 256 * i;
        const int cl = s >> 5;           // 0..31
        const int pq = s & 31;           // 0..31
        const int p  = pbase + pq * 4;
        if (p < NP) {
            const float4 v = *reinterpret_cast<const float4*>(
                xbase + (size_t)cl * TSTRIDE + p);
            const int sidx = cl * 33 + pq;
            tiles[0 * 1057 + sidx] = v.x;
            tiles[1 * 1057 + sidx] = v.y;
            tiles[2 * 1057 + sidx] = v.z;
            tiles[3 * 1057 + sidx] = v.w;
        }
    }
    __syncthreads();

    // c-quad dots in transposed order (fixed order -> deterministic)
    #pragma unroll
    for (int i = 0; i < 4; ++i) {
        const int s  = tid + 256 * i;
        const int cq = s & 7;            // 0..7
        const int pl = s >> 3;           // 0..127
        const int pg = pbase + pl;
        if (pg < NP) {
            const int j  = pl & 3;
            const int pq = pl >> 2;
            const float wx = tiles[j * 1057 + (4 * cq + 0) * 33 + pq];
            const float wy = tiles[j * 1057 + (4 * cq + 1) * 33 + pq];
            const float wz = tiles[j * 1057 + (4 * cq + 2) * 33 + pq];
            const float ww = tiles[j * 1057 + (4 * cq + 3) * 33 + pq];
            part[pl * 9 + cq] = fmaf(cls_s[4 * cq + 0], wx,
                                fmaf(cls_s[4 * cq + 1], wy,
                                fmaf(cls_s[4 * cq + 2], wz,
                                     cls_s[4 * cq + 3] * ww)));
        }
    }
    __syncthreads();

    if (tid < 128) {
        const int pg = pbase + tid;
        if (pg < NP) {
            const float* pr = &part[tid * 9];
            g_spart[b][ct][pg] = ((pr[0] + pr[1]) + (pr[2] + pr[3]))
                               + ((pr[4] + pr[5]) + (pr[6] + pr[7]));
        }
    }
}

// ---------------------------------------------------------------------------
// K2 (fused, R5-identical structure): heterogeneous grid, 256 threads.
//   blocks 0..15       : per-b reduce + bitonic sort 512 (desc score, asc idx
//                        tiebreak = lax.top_k semantics), posmap, cls rows.
//   blocks 16..16+1535 : frame-1 transpose copy, 32c x 128p tiles, float4
//                        both gmem sides, conflict-free component-split smem.
// The ~3us sort hides under the ~7us frame-1 stream.
// ---------------------------------------------------------------------------
__global__ void __launch_bounds__(256) k_mid(const float* __restrict__ x,
                                             const float* __restrict__ cls,
                                             float* __restrict__ out)
{
    __shared__ float sv[512];
    __shared__ int   si[512];
    __shared__ float tiles[4][1057];    // stride 1057 == 1 (mod 32)

    const int tid = threadIdx.x;

    if (blockIdx.x < NB) {
        // ---------------- sort path ----------------
        const int b = blockIdx.x;

        for (int e = tid; e < 512; e += 256) {
            float vsum = -CUDART_INF_F;
            if (e < NP) {
                float a0 = 0.f, a1 = 0.f, a2 = 0.f, a3 = 0.f;
                #pragma unroll
                for (int k = 0; k < 32; k += 4) {
                    a0 += g_spart[b][k + 0][e];
                    a1 += g_spart[b][k + 1][e];
                    a2 += g_spart[b][k + 2][e];
                    a3 += g_spart[b][k + 3][e];
                }
                vsum = (a0 + a1) + (a2 + a3);
            }
            sv[e] = vsum;
            si[e] = e;
        }
        __syncthreads();

        // bitonic: 256 threads, one compare-exchange pair per substage
        for (int k = 2; k <= 512; k <<= 1) {
            for (int j = k >> 1; j > 0; j >>= 1) {
                const int l = 2 * tid - (tid & (j - 1));   // l & j == 0
                const int m = l | j;
                const float a = sv[l], c = sv[m];
                const int   ia = si[l], ic = si[m];
                const bool a_after = (a < c) || (a == c && ia > ic);
                const bool dir_desc = ((l & k) == 0);
                if (dir_desc ? a_after : !a_after) {
                    sv[l] = c; sv[m] = a; si[l] = ic; si[m] = ia;
                }
                __syncthreads();
            }
        }

        for (int p = tid; p < NP; p += 256) g_posmap[b][p] = -1;
        __syncthreads();
        if (tid < NK) g_posmap[b][si[tid]] = 1 + tid;

        // cls rows: row 0 = cls[b,0,:], row 121 = cls[b,1,:]
        const size_t obase = (size_t)b * ROWS * NC;
        const float4* c4 = reinterpret_cast<const float4*>(cls + (size_t)b * NT * NC);
        float4* o4 = reinterpret_cast<float4*>(out + obase);
        for (int c = tid; c < NC / 4; c += 256) {
            o4[c]                = c4[c];               // row 0   (t=0 cls)
            o4[121 * (NC/4) + c] = c4[(NC/4) + c];      // row 121 (t=1 cls)
        }
    } else {
        // ---------------- frame-1 copy path ----------------
        const int bid = blockIdx.x - NB;     // 0..1535
        const int ct  = bid & 31;            // c tile of 32
        const int rem = bid >> 5;
        const int pt  = rem % 3;             // p tile of 128
        const int b   = rem / 3;             // 0..15

        const float* xbase = x + ((size_t)b * NC + ct * 32) * TSTRIDE + NP; // t=1
        const int pbase = pt * 128;

        #pragma unroll
        for (int i = 0; i < 4; ++i) {
            const int s  = tid + 256 * i;
            const int cl = s >> 5;           // 0..31
            const int pq = s & 31;           // 0..31
            const int p  = pbase + pq * 4;
            if (p < NP) {
                const float4 v = *reinterpret_cast<const float4*>(
                    xbase + (size_t)cl * TSTRIDE + p);
                const int idx = cl * 33 + pq;
                tiles[0][idx] = v.x;
                tiles[1][idx] = v.y;
                tiles[2][idx] = v.z;
                tiles[3][idx] = v.w;
            }
        }
        __syncthreads();

        const size_t obase = (size_t)b * ROWS * NC;
        #pragma unroll
        for (int i = 0; i < 4; ++i) {
            const int s  = tid + 256 * i;
            const int cq = s & 7;            // 0..7
            const int pl = s >> 3;           // 0..127
            const int pg = pbase + pl;
            if (pg < NP) {
                const int row = 122 + pg;
                const int j  = pl & 3;
                const int pq = pl >> 2;
                float4 w;
                w.x = tiles[j][(4 * cq + 0) * 33 + pq];
                w.y = tiles[j][(4 * cq + 1) * 33 + pq];
                w.z = tiles[j][(4 * cq + 2) * 33 + pq];
                w.w = tiles[j][(4 * cq + 3) * 33 + pq];
                *reinterpret_cast<float4*>(
                    out + obase + (size_t)row * NC + ct * 32 + cq * 4) = w;
            }
        }
    }
}

// ---------------------------------------------------------------------------
// K3 (R5-identical): frame-0 selective transpose copy (f0 L2-warm from K1).
// grid (32, 3, 16), block 256. Only rows with posmap >= 0 are stored.
// ---------------------------------------------------------------------------
__global__ void __launch_bounds__(256) k_copy0(const float* __restrict__ x,
                                               float* __restrict__ out)
{
    const int ct = blockIdx.x;          // 0..31
    const int pt = blockIdx.y;          // 0..2
    const int b  = blockIdx.z;
    const int tid = threadIdx.x;

    __shared__ float tiles[4][1057];

    const float* xbase = x + ((size_t)b * NC + ct * 32) * TSTRIDE;  // t=0
    const int pbase = pt * 128;

    #pragma unroll
    for (int i = 0; i < 4; ++i) {
        const int s  = tid + 256 * i;
        const int cl = s >> 5;
        const int pq = s & 31;
        const int p  = pbase + pq * 4;
        if (p < NP) {
            const float4 v = *reinterpret_cast<const float4*>(
                xbase + (size_t)cl * TSTRIDE + p);
            const int idx = cl * 33 + pq;
            tiles[0][idx] = v.x;
            tiles[1][idx] = v.y;
            tiles[2][idx] = v.z;
            tiles[3][idx] = v.w;
        }
    }
    __syncthreads();

    const size_t obase = (size_t)b * ROWS * NC;
    #pragma unroll
    for (int i = 0; i < 4; ++i) {
        const int s  = tid + 256 * i;
        const int cq = s & 7;
        const int pl = s >> 3;
        const int pg = pbase + pl;
        if (pg < NP) {
            const int row = g_posmap[b][pg];
            if (row >= 0) {
                const int j  = pl & 3;
                const int pq = pl >> 2;
                float4 w;
                w.x = tiles[j][(4 * cq + 0) * 33 + pq];
                w.y = tiles[j][(4 * cq + 1) * 33 + pq];
                w.z = tiles[j][(4 * cq + 2) * 33 + pq];
                w.w = tiles[j][(4 * cq + 3) * 33 + pq];
                *reinterpret_cast<float4*>(
                    out + obase + (size_t)row * NC + ct * 32 + cq * 4) = w;
            }
        }
    }
}

// ---------------------------------------------------------------------------
extern "C" void kernel_launch(void* const* d_in, const int* in_sizes, int n_in,
                              void* d_out, int out_size)
{
    const float* x   = (const float*)d_in[0];   // [16,1024,16,12,30]
    const float* cls = (const float*)d_in[1];   // [16,16,1024]
    float* out = (float*)d_out;                 // [16,482,1024]

    k_scores<<<1536, 256>>>(x, cls);
    k_mid<<<NB + 1536, 256>>>(x, cls, out);
    k_copy0<<<dim3(32, 3, NB), 256>>>(x, out);
}